// round 2
// baseline (speedup 1.0000x reference)
#include <cuda_runtime.h>
#include <math.h>

#define BSZ 64
#define NN 512
#define DD 256
#define BIGC 1.0e9f

__device__ float g_eA[BSZ*NN*DD];
__device__ float g_eB[BSZ*NN*DD];
__device__ float g_nA[BSZ*NN];
__device__ float g_nB[BSZ*NN];
__device__ float g_K[(size_t)BSZ*NN*NN];
__device__ float g_u[BSZ*NN];
__device__ float g_v[BSZ*NN];
__device__ int   g_cA[BSZ*NN];
__device__ int   g_cB[BSZ*NN];
__device__ double g_acc[3];

__global__ void zero_acc_kernel() {
    if (threadIdx.x < 3) g_acc[threadIdx.x] = 0.0;
}

__global__ void class_argmax_kernel(const float* __restrict__ la,
                                    const float* __restrict__ lb) {
    int t = blockIdx.x * blockDim.x + threadIdx.x;
    if (t >= BSZ*NN) return;
    float4 a = ((const float4*)la)[t];
    int ba = 0; float bv = a.x;
    if (a.y > bv) { bv = a.y; ba = 1; }
    if (a.z > bv) { bv = a.z; ba = 2; }
    if (a.w > bv) { bv = a.w; ba = 3; }
    g_cA[t] = ba;
    float4 b = ((const float4*)lb)[t];
    int bb = 0; bv = b.x;
    if (b.y > bv) { bv = b.y; bb = 1; }
    if (b.z > bv) { bv = b.z; bb = 2; }
    if (b.w > bv) { bv = b.w; bb = 3; }
    g_cB[t] = bb;
}

// LN row epilogue: v[8] holds this lane's 8 pre-activation values of a 256-wide
// row distributed across 32 lanes (cols lane*4..+3 and 128+lane*4..+3).
__device__ __forceinline__ void ln_row(float v[8],
    const float4& g0, const float4& g1, const float4& e0, const float4& e1,
    float* o)
{
    float s = 0.f, sq = 0.f;
    #pragma unroll
    for (int j = 0; j < 8; j++) {
        v[j] = v[j] > 0.f ? v[j] : 0.01f * v[j];
        s += v[j]; sq += v[j]*v[j];
    }
    #pragma unroll
    for (int off = 16; off; off >>= 1) {
        s  += __shfl_xor_sync(0xffffffffu, s, off);
        sq += __shfl_xor_sync(0xffffffffu, sq, off);
    }
    float mean = s * (1.f/256.f);
    float var  = sq * (1.f/256.f) - mean*mean;
    float rstd = rsqrtf(var + 1e-5f);
    o[0] = (v[0]-mean)*rstd*g0.x + e0.x;
    o[1] = (v[1]-mean)*rstd*g0.y + e0.y;
    o[2] = (v[2]-mean)*rstd*g0.z + e0.z;
    o[3] = (v[3]-mean)*rstd*g0.w + e0.w;
    o[4] = (v[4]-mean)*rstd*g1.x + e1.x;
    o[5] = (v[5]-mean)*rstd*g1.y + e1.y;
    o[6] = (v[6]-mean)*rstd*g1.z + e1.z;
    o[7] = (v[7]-mean)*rstd*g1.w + e1.w;
}

// Fused 2-layer MLP+LN embed. Block: 64 rows x 256 cols, 256 threads.
// Warp w owns rows w*8..+7; lane owns cols {lane*4..+3, 128+lane*4..+3}.
#define EMBED_SMEM ((64*256 + 16*256 + 64*16) * 4)

__global__ __launch_bounds__(256)
void embed_kernel(const float* __restrict__ xA, const float* __restrict__ xB,
                  const float* __restrict__ W1, const float* __restrict__ b1,
                  const float* __restrict__ g1, const float* __restrict__ be1,
                  const float* __restrict__ W2, const float* __restrict__ b2,
                  const float* __restrict__ g2, const float* __restrict__ be2)
{
    extern __shared__ float sm[];
    float* Hs = sm;              // 64*256
    float* Ws = sm + 64*256;     // 16*256
    float* As = Ws + 16*256;     // 64*16

    const float* X  = blockIdx.y ? xB   : xA;
    float* E        = blockIdx.y ? g_eB : g_eA;
    float* NRM      = blockIdx.y ? g_nB : g_nA;

    const int tid  = threadIdx.x;
    const int lane = tid & 31;
    const int warp = tid >> 5;
    const int row0 = blockIdx.x * 64;
    const int wr   = warp * 8;
    const int c0   = lane * 4;
    const int c1   = 128 + lane * 4;

    float acc[8][8];
    #pragma unroll
    for (int r = 0; r < 8; r++)
        #pragma unroll
        for (int c = 0; c < 8; c++) acc[r][c] = 0.f;

    // stage 1: h = LN(leaky(x@W1+b1))
    for (int kt = 0; kt < 16; kt++) {
        {
            int rr = tid >> 2, cq = (tid & 3) << 2;
            *(float4*)(As + rr*16 + cq) =
                *(const float4*)(X + (size_t)(row0 + rr)*DD + kt*16 + cq);
            const float4* Wv = (const float4*)(W1 + kt*16*DD);
            float4* Wd = (float4*)Ws;
            #pragma unroll
            for (int i = 0; i < 4; i++) Wd[tid + i*256] = Wv[tid + i*256];
        }
        __syncthreads();
        #pragma unroll
        for (int kk = 0; kk < 16; kk++) {
            float4 w0 = *(const float4*)(Ws + kk*256 + c0);
            float4 w1 = *(const float4*)(Ws + kk*256 + c1);
            #pragma unroll
            for (int r = 0; r < 8; r++) {
                float a = As[(wr + r)*16 + kk];
                acc[r][0] = fmaf(a, w0.x, acc[r][0]);
                acc[r][1] = fmaf(a, w0.y, acc[r][1]);
                acc[r][2] = fmaf(a, w0.z, acc[r][2]);
                acc[r][3] = fmaf(a, w0.w, acc[r][3]);
                acc[r][4] = fmaf(a, w1.x, acc[r][4]);
                acc[r][5] = fmaf(a, w1.y, acc[r][5]);
                acc[r][6] = fmaf(a, w1.z, acc[r][6]);
                acc[r][7] = fmaf(a, w1.w, acc[r][7]);
            }
        }
        __syncthreads();
    }
    {
        float4 bv0 = *(const float4*)(b1 + c0), bv1 = *(const float4*)(b1 + c1);
        float4 gv0 = *(const float4*)(g1 + c0), gv1 = *(const float4*)(g1 + c1);
        float4 ev0 = *(const float4*)(be1 + c0), ev1 = *(const float4*)(be1 + c1);
        #pragma unroll
        for (int r = 0; r < 8; r++) {
            float v[8], o[8];
            v[0]=acc[r][0]+bv0.x; v[1]=acc[r][1]+bv0.y; v[2]=acc[r][2]+bv0.z; v[3]=acc[r][3]+bv0.w;
            v[4]=acc[r][4]+bv1.x; v[5]=acc[r][5]+bv1.y; v[6]=acc[r][6]+bv1.z; v[7]=acc[r][7]+bv1.w;
            ln_row(v, gv0, gv1, ev0, ev1, o);
            *(float4*)(Hs + (wr + r)*256 + c0) = make_float4(o[0],o[1],o[2],o[3]);
            *(float4*)(Hs + (wr + r)*256 + c1) = make_float4(o[4],o[5],o[6],o[7]);
        }
    }
    __syncthreads();
    #pragma unroll
    for (int r = 0; r < 8; r++)
        #pragma unroll
        for (int c = 0; c < 8; c++) acc[r][c] = 0.f;

    // stage 2: e = LN(leaky(h@W2+b2))
    for (int kt = 0; kt < 16; kt++) {
        {
            const float4* Wv = (const float4*)(W2 + kt*16*DD);
            float4* Wd = (float4*)Ws;
            #pragma unroll
            for (int i = 0; i < 4; i++) Wd[tid + i*256] = Wv[tid + i*256];
        }
        __syncthreads();
        #pragma unroll
        for (int kk = 0; kk < 16; kk++) {
            float4 w0 = *(const float4*)(Ws + kk*256 + c0);
            float4 w1 = *(const float4*)(Ws + kk*256 + c1);
            #pragma unroll
            for (int r = 0; r < 8; r++) {
                float a = Hs[(wr + r)*256 + kt*16 + kk];
                acc[r][0] = fmaf(a, w0.x, acc[r][0]);
                acc[r][1] = fmaf(a, w0.y, acc[r][1]);
                acc[r][2] = fmaf(a, w0.z, acc[r][2]);
                acc[r][3] = fmaf(a, w0.w, acc[r][3]);
                acc[r][4] = fmaf(a, w1.x, acc[r][4]);
                acc[r][5] = fmaf(a, w1.y, acc[r][5]);
                acc[r][6] = fmaf(a, w1.z, acc[r][6]);
                acc[r][7] = fmaf(a, w1.w, acc[r][7]);
            }
        }
        __syncthreads();
    }
    {
        float4 bv0 = *(const float4*)(b2 + c0), bv1 = *(const float4*)(b2 + c1);
        float4 gv0 = *(const float4*)(g2 + c0), gv1 = *(const float4*)(g2 + c1);
        float4 ev0 = *(const float4*)(be2 + c0), ev1 = *(const float4*)(be2 + c1);
        #pragma unroll
        for (int r = 0; r < 8; r++) {
            float v[8], o[8];
            v[0]=acc[r][0]+bv0.x; v[1]=acc[r][1]+bv0.y; v[2]=acc[r][2]+bv0.z; v[3]=acc[r][3]+bv0.w;
            v[4]=acc[r][4]+bv1.x; v[5]=acc[r][5]+bv1.y; v[6]=acc[r][6]+bv1.z; v[7]=acc[r][7]+bv1.w;
            ln_row(v, gv0, gv1, ev0, ev1, o);
            float ns = o[0]*o[0]+o[1]*o[1]+o[2]*o[2]+o[3]*o[3]
                     + o[4]*o[4]+o[5]*o[5]+o[6]*o[6]+o[7]*o[7];
            #pragma unroll
            for (int off = 16; off; off >>= 1)
                ns += __shfl_xor_sync(0xffffffffu, ns, off);
            size_t grow = (size_t)(row0 + wr + r);
            *(float4*)(E + grow*DD + c0) = make_float4(o[0],o[1],o[2],o[3]);
            *(float4*)(E + grow*DD + c1) = make_float4(o[4],o[5],o[6],o[7]);
            if (lane == 0) NRM[grow] = ns;
        }
    }
}

// cdist + cost_class + in/out loss partial sums + K = exp(-2*cost_class).
// Batched GEMM eA@eB^T, 128x128 tile, 256 threads, 8x8 microtile.
__global__ __launch_bounds__(256)
void cost_kernel(const float* __restrict__ pa, const float* __restrict__ pb)
{
    __shared__ __align__(16) float Ast[16][132];
    __shared__ __align__(16) float Bst[16][132];
    __shared__ float redi[8], redo[8];

    const int b  = blockIdx.z;
    const int ti = blockIdx.y;
    const int tj = blockIdx.x;
    const int tid = threadIdx.x;
    const int ty = tid >> 4;
    const int tx = tid & 15;

    const float* Ab = g_eA + (size_t)b*NN*DD + (size_t)ti*128*DD;
    const float* Bb = g_eB + (size_t)b*NN*DD + (size_t)tj*128*DD;

    float acc[8][8];
    #pragma unroll
    for (int r = 0; r < 8; r++)
        #pragma unroll
        for (int c = 0; c < 8; c++) acc[r][c] = 0.f;

    for (int kt = 0; kt < 16; kt++) {
        #pragma unroll
        for (int s = 0; s < 2; s++) {
            int idx = tid + s*256;
            int row = idx >> 2, cq = (idx & 3) << 2;
            float4 av = *(const float4*)(Ab + (size_t)row*DD + kt*16 + cq);
            Ast[cq+0][row]=av.x; Ast[cq+1][row]=av.y; Ast[cq+2][row]=av.z; Ast[cq+3][row]=av.w;
            float4 bv = *(const float4*)(Bb + (size_t)row*DD + kt*16 + cq);
            Bst[cq+0][row]=bv.x; Bst[cq+1][row]=bv.y; Bst[cq+2][row]=bv.z; Bst[cq+3][row]=bv.w;
        }
        __syncthreads();
        #pragma unroll
        for (int kk = 0; kk < 16; kk++) {
            float4 a0 = *(const float4*)(&Ast[kk][ty*4]);
            float4 a1 = *(const float4*)(&Ast[kk][64 + ty*4]);
            float4 b0 = *(const float4*)(&Bst[kk][tx*4]);
            float4 b1 = *(const float4*)(&Bst[kk][64 + tx*4]);
            float ar[8] = {a0.x,a0.y,a0.z,a0.w,a1.x,a1.y,a1.z,a1.w};
            float br[8] = {b0.x,b0.y,b0.z,b0.w,b1.x,b1.y,b1.z,b1.w};
            #pragma unroll
            for (int r = 0; r < 8; r++)
                #pragma unroll
                for (int c = 0; c < 8; c++)
                    acc[r][c] = fmaf(ar[r], br[c], acc[r][c]);
        }
        __syncthreads();
    }

    float ni[8], pav[8]; int cai[8];
    float njv[8], pbv[8]; int cbj[8];
    #pragma unroll
    for (int r = 0; r < 8; r++) {
        int il = ti*128 + ((r < 4) ? ty*4 + r : 64 + ty*4 + (r-4));
        int gi = b*NN + il;
        ni[r] = g_nA[gi]; pav[r] = pa[gi]; cai[r] = g_cA[gi];
    }
    #pragma unroll
    for (int c = 0; c < 8; c++) {
        int jl = tj*128 + ((c < 4) ? tx*4 + c : 64 + tx*4 + (c-4));
        int gj = b*NN + jl;
        njv[c] = g_nB[gj]; pbv[c] = pb[gj]; cbj[c] = g_cB[gj];
    }

    float sin = 0.f, sout = 0.f;
    #pragma unroll
    for (int r = 0; r < 8; r++) {
        int il = ti*128 + ((r < 4) ? ty*4 + r : 64 + ty*4 + (r-4));
        size_t rowb = ((size_t)(b*NN + il)) * NN;
        #pragma unroll
        for (int cg = 0; cg < 2; cg++) {
            float kv[4];
            #pragma unroll
            for (int c4 = 0; c4 < 4; c4++) {
                int c = cg*4 + c4;
                float sq   = ni[r] + njv[c] - 2.f*acc[r][c];
                float cost = sqrtf(fmaxf(sq, 0.f));
                float pm   = pav[r]*pbv[c];
                float cc   = cost + (BIGC - BIGC*pm);
                float w    = cc * pm;
                if (cai[r] == cbj[c]) sin += w; else sout += w;
                kv[c4] = __expf(-2.f*cc);
            }
            *(float4*)(g_K + rowb + tj*128 + cg*64 + tx*4) =
                make_float4(kv[0],kv[1],kv[2],kv[3]);
        }
    }
    #pragma unroll
    for (int off = 16; off; off >>= 1) {
        sin  += __shfl_xor_sync(0xffffffffu, sin,  off);
        sout += __shfl_xor_sync(0xffffffffu, sout, off);
    }
    int lane = tid & 31, warp = tid >> 5;
    if (lane == 0) { redi[warp] = sin; redo[warp] = sout; }
    __syncthreads();
    if (tid == 0) {
        float a = 0.f, o2 = 0.f;
        #pragma unroll
        for (int w = 0; w < 8; w++) { a += redi[w]; o2 += redo[w]; }
        atomicAdd(&g_acc[0], (double)a);
        atomicAdd(&g_acc[1], (double)o2);
    }
}

// Sinkhorn, 1 CTA per batch, K resident in L2.
__global__ __launch_bounds__(512)
void sinkhorn_kernel()
{
    __shared__ __align__(16) float su[NN];
    __shared__ __align__(16) float sv[NN];
    __shared__ __align__(16) float part[4][NN];

    const int b = blockIdx.x;
    const float* Kb = g_K + (size_t)b*NN*NN;
    const int tid  = threadIdx.x;
    const int lane = tid & 31;
    const int warp = tid >> 5;
    const int grp  = tid >> 7;
    const int jc   = (tid & 127) * 4;

    su[tid] = 1.f/512.f;
    __syncthreads();

    for (int it = 0; it < 10; it++) {
        // v = b / (K^T u)
        float4 accv = make_float4(0.f,0.f,0.f,0.f);
        const int i0 = grp * 128;
        #pragma unroll 4
        for (int i = 0; i < 128; i++) {
            float4 kv = *(const float4*)(Kb + (size_t)(i0 + i)*NN + jc);
            float ui = su[i0 + i];
            accv.x = fmaf(kv.x, ui, accv.x);
            accv.y = fmaf(kv.y, ui, accv.y);
            accv.z = fmaf(kv.z, ui, accv.z);
            accv.w = fmaf(kv.w, ui, accv.w);
        }
        *(float4*)(&part[grp][jc]) = accv;
        __syncthreads();
        {
            float y = part[0][tid] + part[1][tid] + part[2][tid] + part[3][tid];
            sv[tid] = (1.f/512.f) / y;
        }
        __syncthreads();
        // u = a / (K v), warp per row
        for (int rr = 0; rr < 32; rr++) {
            int i = warp*32 + rr;
            const float4* kr = (const float4*)(Kb + (size_t)i*NN);
            float s = 0.f;
            #pragma unroll
            for (int q = 0; q < 4; q++) {
                float4 kv = kr[lane + q*32];
                float4 vv = *(const float4*)(sv + (lane + q*32)*4);
                s = fmaf(kv.x, vv.x, s);
                s = fmaf(kv.y, vv.y, s);
                s = fmaf(kv.z, vv.z, s);
                s = fmaf(kv.w, vv.w, s);
            }
            #pragma unroll
            for (int off = 16; off; off >>= 1)
                s += __shfl_xor_sync(0xffffffffu, s, off);
            if (lane == 0) su[i] = (1.f/512.f) / s;
        }
        __syncthreads();
    }
    g_u[b*NN + tid] = su[tid];
    g_v[b*NN + tid] = sv[tid];
}

__global__ void sup_kernel(const float* __restrict__ rel,
                           const float* __restrict__ pa)
{
    __shared__ float red[8];
    const size_t total4 = (size_t)BSZ*NN*NN/4;
    float lacc = 0.f;
    for (size_t idx = (size_t)blockIdx.x*blockDim.x + threadIdx.x; idx < total4;
         idx += (size_t)gridDim.x*blockDim.x) {
        size_t e = idx * 4;
        int b = (int)(e >> 18);
        int i = (int)((e >> 9) & 511);
        int j = (int)(e & 511);
        float4 kv = ((const float4*)g_K)[idx];
        float4 rv = ((const float4*)rel)[idx];
        float ui  = g_u[b*NN + i] * 512.f;
        float pai = pa[b*NN + i];
        float4 vv = *(const float4*)(g_v + b*NN + j);
        float d0 = ui*kv.x*vv.x - rv.x;
        float d1 = ui*kv.y*vv.y - rv.y;
        float d2 = ui*kv.z*vv.z - rv.z;
        float d3 = ui*kv.w*vv.w - rv.w;
        lacc += pai * (d0*d0 + d1*d1 + d2*d2 + d3*d3);
    }
    #pragma unroll
    for (int off = 16; off; off >>= 1)
        lacc += __shfl_xor_sync(0xffffffffu, lacc, off);
    int lane = threadIdx.x & 31, warp = threadIdx.x >> 5;
    if (lane == 0) red[warp] = lacc;
    __syncthreads();
    if (threadIdx.x == 0) {
        float s = 0.f;
        #pragma unroll
        for (int w = 0; w < 8; w++) s += red[w];
        atomicAdd(&g_acc[2], (double)s);
    }
}

__global__ void finalize_kernel(const float* __restrict__ pa, float* __restrict__ out)
{
    __shared__ float red[256];
    float s = 0.f;
    for (int i = threadIdx.x; i < BSZ*NN; i += 256) s += pa[i];
    red[threadIdx.x] = s;
    __syncthreads();
    for (int off = 128; off; off >>= 1) {
        if (threadIdx.x < off) red[threadIdx.x] += red[threadIdx.x + off];
        __syncthreads();
    }
    if (threadIdx.x == 0) {
        double M = (double)BSZ * (double)NN * (double)NN;
        out[0] = (float)(g_acc[0]/M - g_acc[1]/M + 10.0*(g_acc[2]/(double)red[0]));
    }
}

extern "C" void kernel_launch(void* const* d_in, const int* in_sizes, int n_in,
                              void* d_out, int out_size)
{
    const float* la  = (const float*)d_in[0];
    const float* lb  = (const float*)d_in[1];
    const float* xA  = (const float*)d_in[2];
    const float* xB  = (const float*)d_in[3];
    const float* rel = (const float*)d_in[4];
    const float* pa  = (const float*)d_in[5];
    const float* pb  = (const float*)d_in[6];
    const float* W1  = (const float*)d_in[7];
    const float* b1  = (const float*)d_in[8];
    const float* g1  = (const float*)d_in[9];
    const float* be1 = (const float*)d_in[10];
    const float* W2  = (const float*)d_in[11];
    const float* b2  = (const float*)d_in[12];
    const float* g2  = (const float*)d_in[13];
    const float* be2 = (const float*)d_in[14];
    float* out = (float*)d_out;

    cudaFuncSetAttribute(embed_kernel,
                         cudaFuncAttributeMaxDynamicSharedMemorySize, EMBED_SMEM);

    zero_acc_kernel<<<1, 32>>>();
    class_argmax_kernel<<<(BSZ*NN + 255)/256, 256>>>(la, lb);
    embed_kernel<<<dim3(BSZ*NN/64, 2), 256, EMBED_SMEM>>>(
        xA, xB, W1, b1, g1, be1, W2, b2, g2, be2);
    cost_kernel<<<dim3(4, 4, BSZ), 256>>>(pa, pb);
    sinkhorn_kernel<<<BSZ, 512>>>();
    sup_kernel<<<2048, 256>>>(rel, pa);
    finalize_kernel<<<1, 256>>>(pa, out);
}